// round 5
// baseline (speedup 1.0000x reference)
#include <cuda_runtime.h>
#include <cstdint>

// Problem constants (fixed by setup_inputs)
#define BT 4
#define NV 20000
#define NF 40000
#define HH 256
#define WW 256
#define SS 2048
#define VCAP 20480            // NV padded; = VS * VPB
#define VS 16                 // vert splits
#define SG 8                  // sample groups (256 samples each, 8/lane)
#define VPB (VCAP / VS)       // 1280 verts per block = one tile
#define GRID (VS * BT * SG)   // 512 blocks
#define MASK_PENALTY 1000.0f
#define BIGW 3.0e37f

typedef unsigned long long u64;

// Scratch (no dynamic allocation allowed)
__device__ unsigned char g_visible[BT * NV];
__device__ u64           g_vert8[(size_t)BT * VCAP * 4];  // {x,x},{y,y},{z,z},{w,w}
__device__ int           g_hasInv[BT];
__device__ int           g_min[BT * SS];                  // encoded float mins
__device__ int           g_done = 0;

// ---- packed f32x2 helpers (sm_103a) ----
__device__ __forceinline__ u64 pack2(float lo, float hi) {
    u64 r; asm("mov.b64 %0, {%1, %2};" : "=l"(r) : "f"(lo), "f"(hi)); return r;
}
__device__ __forceinline__ void unpack2(u64 v, float& lo, float& hi) {
    asm("mov.b64 {%0, %1}, %2;" : "=f"(lo), "=f"(hi) : "l"(v));
}
__device__ __forceinline__ u64 fma2(u64 a, u64 b, u64 c) {
    u64 d; asm("fma.rn.f32x2 %0, %1, %2, %3;" : "=l"(d) : "l"(a), "l"(b), "l"(c)); return d;
}
// order-preserving float -> signed int map (involution)
__device__ __forceinline__ int enc(float f) {
    int k = __float_as_int(f);
    return k >= 0 ? k : (k ^ 0x7FFFFFFF);
}

// ---------------------------------------------------------------------------
// K1: clear visibility flags, hasInv flags, g_min, g_done
// ---------------------------------------------------------------------------
__global__ void k_clear() {
    int i = blockIdx.x * blockDim.x + threadIdx.x;
    uint32_t* p = (uint32_t*)g_visible;          // BT*NV bytes = 20000 words
    if (i < (BT * NV) / 4) p[i] = 0u;
    if (i < BT * SS) g_min[i] = enc(BIGW);
    if (i < BT) g_hasInv[i] = 0;
    if (i == 0) g_done = 0;
}

// ---------------------------------------------------------------------------
// K2: visibility scatter (faces / pix_to_face are int32 in memory)
// ---------------------------------------------------------------------------
__global__ void k_vis(const int* __restrict__ p2f,
                      const int* __restrict__ faces) {
    int p = blockIdx.x * blockDim.x + threadIdx.x;
    if (p >= BT * HH * WW) return;
    int fi = p2f[p];
    if ((unsigned)fi >= (unsigned)(BT * NF)) return;   // also rejects -1
    int b  = fi / NF;
    const int* fr = faces + fi * 3;
    int base = b * NV;
    int v0 = fr[0], v1 = fr[1], v2 = fr[2];
    if ((unsigned)v0 < (unsigned)NV) g_visible[base + v0] = 1;
    if ((unsigned)v1 < (unsigned)NV) g_visible[base + v1] = 1;
    if ((unsigned)v2 < (unsigned)NV) g_visible[base + v2] = 1;
}

// ---------------------------------------------------------------------------
// K3: verts -> duplicated packed layout {x,x}{y,y}{z,z}{w,w},
// w = 0.5*|v|^2 if visible else BIGW; padding rows get BIGW.
// ---------------------------------------------------------------------------
__global__ void k_xform(const float* __restrict__ verts) {
    int i = blockIdx.x * blockDim.x + threadIdx.x;
    if (i >= BT * VCAP) return;
    int b = i / VCAP;
    int v = i - b * VCAP;
    float x = 0.f, y = 0.f, z = 0.f, w = BIGW;
    if (v < NV) {
        int idx = (b * NV + v) * 3;
        x = verts[idx + 0]; y = verts[idx + 1]; z = verts[idx + 2];
        bool vis = (g_visible[b * NV + v] != 0);
        if (vis) w = 0.5f * (x * x + y * y + z * z);
        else     g_hasInv[b] = 1;
    }
    u64* o = g_vert8 + (size_t)i * 4;
    o[0] = pack2(x, x); o[1] = pack2(y, y); o[2] = pack2(z, z); o[3] = pack2(w, w);
}

// ---------------------------------------------------------------------------
// K4: main fused min-score kernel (packed f32x2 math) + fused final reduce.
// Grid: 512 blocks = VS(16) x BT(4) x SG(8), 4 blocks/SM -> one wave.
// Block: 256 samples (8/lane as 4 packed pairs) x 1280 verts (one tile).
// score = w - s.v via 3 fma.f32x2 per packed sample-pair; mins folded into
// g_min via order-preserving int atomicMin. Last block finishes the loss.
// ---------------------------------------------------------------------------
__global__ void __launch_bounds__(256, 4)
k_main(const float* __restrict__ bds, float* __restrict__ out) {
    __shared__ __align__(16) u64 sv[VPB * 4];   // 40KB
    __shared__ float sred[8][256];              // 8KB  (reused by last block)

    const int bx   = blockIdx.x;          // 0..511
    const int vs   = bx & 15;
    const int b    = (bx >> 4) & 3;
    const int sg   = bx >> 6;              // 0..7
    const int t    = threadIdx.x;
    const int wid  = t >> 5;
    const int lane = t & 31;

    const float4* bp = ((const float4*)bds) + b * SS + sg * 256;

    u64 nx2[4], ny2[4], nz2[4];
    float mlo[4], mhi[4];
    #pragma unroll
    for (int p = 0; p < 4; p++) {
        float4 sa = bp[lane + 64 * p];         // sample 2p
        float4 sb = bp[lane + 64 * p + 32];    // sample 2p+1
        nx2[p] = pack2(-sa.x, -sb.x);
        ny2[p] = pack2(-sa.y, -sb.y);
        nz2[p] = pack2(-sa.z, -sb.z);
        mlo[p] = BIGW; mhi[p] = BIGW;
    }

    // cooperative tile load: VPB*4 u64 = 2560 uint4, 10 per thread
    {
        const uint4* src = (const uint4*)(g_vert8 + (size_t)(b * VCAP + vs * VPB) * 4);
        uint4* dst = (uint4*)sv;
        #pragma unroll
        for (int j = 0; j < 10; j++)
            dst[t + j * 256] = src[t + j * 256];
    }
    __syncthreads();

    // 160 verts per warp; plain C++ shared loads -> schedulable LDS.128
    const ulonglong2* wv = ((const ulonglong2*)sv) + wid * 160 * 2;
    #pragma unroll 4
    for (int i = 0; i < 160; i++) {
        ulonglong2 a = wv[2 * i];        // {xx, yy}
        ulonglong2 c = wv[2 * i + 1];    // {zz, ww}
        #pragma unroll
        for (int p = 0; p < 4; p++) {
            u64 acc = fma2(a.x, nx2[p], fma2(a.y, ny2[p], fma2(c.x, nz2[p], c.y)));
            float lo, hi; unpack2(acc, lo, hi);
            mlo[p] = fminf(mlo[p], lo);
            mhi[p] = fminf(mhi[p], hi);
        }
    }

    #pragma unroll
    for (int p = 0; p < 4; p++) {
        sred[wid][p * 64 + lane]      = mlo[p];
        sred[wid][p * 64 + 32 + lane] = mhi[p];
    }
    __syncthreads();

    // cross-warp min for sample (sg*256 + t), fold into global
    {
        float mm = sred[0][t];
        #pragma unroll
        for (int w = 1; w < 8; w++) mm = fminf(mm, sred[w][t]);
        atomicMin(&g_min[b * SS + sg * 256 + t], enc(mm));
    }

    // ---- last-block final reduction (replaces separate k_red launch) ----
    __threadfence();
    __syncthreads();                       // all atomicMins of this block fenced
    if (t == 0)
        sred[0][0] = (atomicAdd(&g_done, 1) == GRID - 1) ? 1.0f : 0.0f;
    __syncthreads();
    if (sred[0][0] == 0.0f) return;

    if (t == 0) g_done = 0;                // reset for next graph replay
    __syncthreads();

    float acc = 0.0f;
    const float4* bq = (const float4*)bds;
    #pragma unroll
    for (int k = 0; k < (BT * SS) / 256; k++) {
        int i = t + k * 256;
        int bb = i >> 11;                  // SS = 2048
        int e = g_min[i];
        float m = __int_as_float(e >= 0 ? e : (e ^ 0x7FFFFFFF));
        float4 sm = bq[i];
        float ss2 = sm.x * sm.x + sm.y * sm.y + sm.z * sm.z;
        float dist = 2.0f * m + ss2;
        if (g_hasInv[bb]) dist = fminf(dist, MASK_PENALTY);
        acc += dist * sm.w;                // sample mask (0/1)
    }
    sred[0][t] = acc;
    __syncthreads();
    #pragma unroll
    for (int s = 128; s > 0; s >>= 1) {
        if (t < s) sred[0][t] += sred[0][t + s];
        __syncthreads();
    }
    if (t == 0) out[0] = sred[0][0] * (1.0f / BT);
}

// ---------------------------------------------------------------------------
// Launch
// Inputs (metadata order): verts f32, bds f32, faces int32, pix_to_face int32,
// n_samples (ignored; fixed = 2048). Output: scalar f32.
// ---------------------------------------------------------------------------
extern "C" void kernel_launch(void* const* d_in, const int* in_sizes, int n_in,
                              void* d_out, int out_size) {
    const float* verts = (const float*)d_in[0];
    const float* bds   = (const float*)d_in[1];
    const int*   faces = (const int*)d_in[2];
    const int*   p2f   = (const int*)d_in[3];
    float* out = (float*)d_out;

    k_clear<<<((BT * NV) / 4 + 255) / 256, 256>>>();
    k_vis<<<(BT * HH * WW + 255) / 256, 256>>>(p2f, faces);
    k_xform<<<(BT * VCAP + 255) / 256, 256>>>(verts);
    k_main<<<GRID, 256>>>(bds, out);
}